// round 3
// baseline (speedup 1.0000x reference)
#include <cuda_runtime.h>

// Problem constants
#define CC    512
#define BB    8
#define TT    16
#define ND    32
#define NROW  512           // TT*ND
#define KSZ   7
#define TAU   10            // TT - KSZ + 1
#define LN_EPS 1e-5f
#define NEG_SLOPE 0.01f

// Scratch (no allocations allowed -> __device__ globals)
__device__ float g_norm[BB * NROW * CC];   // normalized rows       (8 MB)
__device__ float g_A[BB * NROW * NROW];    // A = (norm*w) @ norm^T (8 MB)
__device__ int   g_top[BB * NROW * TT];    // argmax indices

// ---------------- f32x2 (Blackwell packed fp32) helpers ----------------
static __device__ __forceinline__ unsigned long long f2pack(float lo, float hi) {
    unsigned long long r;
    asm("mov.b64 %0, {%1, %2};" : "=l"(r) : "f"(lo), "f"(hi));
    return r;
}
static __device__ __forceinline__ void f2unpack(unsigned long long v, float& lo, float& hi) {
    asm("mov.b64 {%0, %1}, %2;" : "=f"(lo), "=f"(hi) : "l"(v));
}
static __device__ __forceinline__ unsigned long long
f2fma(unsigned long long a, unsigned long long b, unsigned long long c) {
    unsigned long long d;
    asm("fma.rn.f32x2 %0, %1, %2, %3;" : "=l"(d) : "l"(a), "l"(b), "l"(c));
    return d;
}

// ---------------- 1) Row L2 normalize (one warp per row) ----------------
__global__ __launch_bounds__(256) void normalize_kernel(const float* __restrict__ lf,
                                                        float* __restrict__ out) {
    int w = (blockIdx.x * blockDim.x + threadIdx.x) >> 5;
    int lane = threadIdx.x & 31;
    if (w >= BB * NROW) return;
    const float4* src = (const float4*)(lf + (size_t)w * CC);
    float4 v[4];
    float s = 0.f;
#pragma unroll
    for (int q = 0; q < 4; q++) {
        v[q] = src[q * 32 + lane];
        s += v[q].x * v[q].x + v[q].y * v[q].y + v[q].z * v[q].z + v[q].w * v[q].w;
    }
#pragma unroll
    for (int off = 16; off; off >>= 1) s += __shfl_xor_sync(0xffffffffu, s, off);
    float nrm = sqrtf(s);
    float inv = 1.0f / fmaxf(nrm, 1e-12f);
    float4* dst = (float4*)(out + (size_t)w * CC);
#pragma unroll
    for (int q = 0; q < 4; q++) {
        v[q].x *= inv; v[q].y *= inv; v[q].z *= inv; v[q].w *= inv;
        dst[q * 32 + lane] = v[q];
    }
}

// ---------------- 2) A = (norm * diag(W)) @ norm^T, fp32x2, 128x128x16 tile ----------------
// C[n][m] = sum_k (Ng[n][k] * w[k]) * Ng[m][k]   per batch
__global__ __launch_bounds__(256) void gemm_diag_kernel(const float* __restrict__ Ng,
                                                        const float* __restrict__ W,
                                                        float* __restrict__ Cg) {
    __shared__ float As[16][132];   // transposed: As[k][row], pre-scaled by w[k]
    __shared__ float Bs[16][132];   // Bs[k][col]
    __shared__ float wS[CC];        // diag(W)

    const int b = blockIdx.z;
    const float* Nb = Ng + (size_t)b * NROW * CC;
    float* Cb = Cg + (size_t)b * NROW * NROW;

    const int rowBase = blockIdx.y * 128;
    const int colBase = blockIdx.x * 128;
    const int tid = threadIdx.x;
    const int tx = tid & 15;    // 16 col-groups of 8
    const int ty = tid >> 4;    // 16 row-groups of 8

    // load diag(W) once (stride 513)
#pragma unroll
    for (int i = tid; i < CC; i += 256) wS[i] = W[(size_t)i * CC + i];

    unsigned long long acc[8][4];
#pragma unroll
    for (int r = 0; r < 8; r++)
#pragma unroll
        for (int p = 0; p < 4; p++) acc[r][p] = 0ull;
    __syncthreads();

    for (int k0 = 0; k0 < CC; k0 += 16) {
        // A tile: 128 rows x 16 k, stored transposed As[k][row], scaled by w
        {
            int q = tid & 3;        // k float4 index
            int r = tid >> 2;       // 0..63
            float w0 = wS[k0 + q * 4 + 0], w1 = wS[k0 + q * 4 + 1];
            float w2 = wS[k0 + q * 4 + 2], w3 = wS[k0 + q * 4 + 3];
#pragma unroll
            for (int h = 0; h < 2; h++) {
                int row = r + h * 64;
                float4 v = *(const float4*)(Nb + (size_t)(rowBase + row) * CC + k0 + q * 4);
                As[q * 4 + 0][row] = v.x * w0;
                As[q * 4 + 1][row] = v.y * w1;
                As[q * 4 + 2][row] = v.z * w2;
                As[q * 4 + 3][row] = v.w * w3;
            }
        }
        // B tile: rows m of norm, k-contiguous, stored transposed Bs[k][m]
        {
            int q = tid & 3;
            int m = tid >> 2;
#pragma unroll
            for (int h = 0; h < 2; h++) {
                int mm = m + h * 64;
                float4 v = *(const float4*)(Nb + (size_t)(colBase + mm) * CC + k0 + q * 4);
                Bs[q * 4 + 0][mm] = v.x;
                Bs[q * 4 + 1][mm] = v.y;
                Bs[q * 4 + 2][mm] = v.z;
                Bs[q * 4 + 3][mm] = v.w;
            }
        }
        __syncthreads();

#pragma unroll
        for (int kk = 0; kk < 16; kk++) {
            float4 a0 = *(const float4*)&As[kk][ty * 8];
            float4 a1 = *(const float4*)&As[kk][ty * 8 + 4];
            float4 b0 = *(const float4*)&Bs[kk][tx * 8];
            float4 b1 = *(const float4*)&Bs[kk][tx * 8 + 4];
            unsigned long long bp[4] = { f2pack(b0.x, b0.y), f2pack(b0.z, b0.w),
                                         f2pack(b1.x, b1.y), f2pack(b1.z, b1.w) };
            float av[8] = { a0.x, a0.y, a0.z, a0.w, a1.x, a1.y, a1.z, a1.w };
#pragma unroll
            for (int r = 0; r < 8; r++) {
                unsigned long long ad = f2pack(av[r], av[r]);
#pragma unroll
                for (int p = 0; p < 4; p++) acc[r][p] = f2fma(ad, bp[p], acc[r][p]);
            }
        }
        __syncthreads();
    }

#pragma unroll
    for (int r = 0; r < 8; r++) {
        int row = rowBase + ty * 8 + r;
        float* cp = Cb + (size_t)row * NROW + colBase + tx * 8;
#pragma unroll
        for (int p = 0; p < 4; p++) {
            float lo, hi;
            f2unpack(acc[r][p], lo, hi);
            *(float2*)(cp + 2 * p) = make_float2(lo, hi);
        }
    }
}

// ---------------- 3) argmax over nd-groups of 32 (one warp per (b,n) row) ----------------
__global__ __launch_bounds__(256) void argmax_kernel(const float* __restrict__ A,
                                                     int* __restrict__ top) {
    int w = (blockIdx.x * blockDim.x + threadIdx.x) >> 5;
    int lane = threadIdx.x & 31;
    if (w >= BB * NROW) return;
    const float* row = A + (size_t)w * NROW;
#pragma unroll
    for (int t = 0; t < TT; t++) {
        float v = row[t * 32 + lane];
        int idx = lane;
#pragma unroll
        for (int off = 16; off; off >>= 1) {
            float ov = __shfl_xor_sync(0xffffffffu, v, off);
            int oi = __shfl_xor_sync(0xffffffffu, idx, off);
            // max, with lowest-index tiebreak (matches jnp.argmax)
            if (ov > v || (ov == v && oi < idx)) { v = ov; idx = oi; }
        }
        if (lane == 0) top[w * TT + t] = idx;
    }
}

// ---------------- 4) gather + depthwise conv + LN + leaky + time-mean ----------------
__global__ __launch_bounds__(256) void conv_ln_kernel(const float* __restrict__ lf,
                                                      const float* __restrict__ cw,
                                                      const float* __restrict__ cb,
                                                      const float* __restrict__ gamma,
                                                      const float* __restrict__ beta,
                                                      const int* __restrict__ top,
                                                      float* __restrict__ out) {
    __shared__ float xf[TT][CC];        // 32 KB gathered features
    __shared__ int sidx[TT];
    __shared__ float rbuf[16];

    const int row = blockIdx.x;         // b*512 + n
    const int b = row >> 9;
    const int tid = threadIdx.x;

    if (tid < TT) sidx[tid] = top[row * TT + tid];
    __syncthreads();

    // gather: xf[t][:] = local_feat[b, t, sidx[t], :]
    for (int i = tid; i < TT * (CC / 4); i += 256) {
        int t = i >> 7;
        int c4 = i & 127;
        const float4* src = (const float4*)(lf + (((size_t)b * TT + t) * ND + sidx[t]) * CC);
        ((float4*)xf[t])[c4] = src[c4];
    }
    __syncthreads();

    const int c0 = tid, c1 = tid + 256;
    float w0[KSZ], w1[KSZ];
#pragma unroll
    for (int j = 0; j < KSZ; j++) { w0[j] = cw[c0 * KSZ + j]; w1[j] = cw[c1 * KSZ + j]; }
    const float bias0 = cb[c0], bias1 = cb[c1];
    const float g0 = gamma[c0], g1 = gamma[c1];
    const float be0 = beta[c0], be1 = beta[c1];
    float acc0 = 0.f, acc1 = 0.f;
    const int lane = tid & 31, warp = tid >> 5;

    for (int tau = 0; tau < TAU; tau++) {
        float y0 = bias0, y1 = bias1;
#pragma unroll
        for (int j = 0; j < KSZ; j++) {
            y0 += w0[j] * xf[tau + j][c0];
            y1 += w1[j] * xf[tau + j][c1];
        }
        // block reduction of sum + sumsq over the 512 channels
        float s = y0 + y1;
        float ss = y0 * y0 + y1 * y1;
#pragma unroll
        for (int off = 16; off; off >>= 1) {
            s  += __shfl_xor_sync(0xffffffffu, s, off);
            ss += __shfl_xor_sync(0xffffffffu, ss, off);
        }
        if (lane == 0) { rbuf[warp] = s; rbuf[8 + warp] = ss; }
        __syncthreads();
        float S = 0.f, SS = 0.f;
#pragma unroll
        for (int k = 0; k < 8; k++) { S += rbuf[k]; SS += rbuf[8 + k]; }
        __syncthreads();
        float mu = S * (1.0f / 512.0f);
        float var = SS * (1.0f / 512.0f) - mu * mu;
        float inv = rsqrtf(var + LN_EPS);
        float l0 = (y0 - mu) * inv * g0 + be0;
        float l1 = (y1 - mu) * inv * g1 + be1;
        acc0 += (l0 >= 0.f) ? l0 : NEG_SLOPE * l0;
        acc1 += (l1 >= 0.f) ? l1 : NEG_SLOPE * l1;
    }
    out[(size_t)row * CC + c0] = acc0 * (1.0f / TAU);
    out[(size_t)row * CC + c1] = acc1 * (1.0f / TAU);
}

// ---------------- launch ----------------
extern "C" void kernel_launch(void* const* d_in, const int* in_sizes, int n_in,
                              void* d_out, int out_size) {
    const float* lf = (const float*)d_in[0];   // local_feat (8,16,32,512)
    // d_in[1] global_feat, d_in[2] pos: unused by the reference
    const float* W  = (const float*)d_in[3];
    const float* cw = (const float*)d_in[4];
    const float* cb = (const float*)d_in[5];
    const float* gm = (const float*)d_in[6];
    const float* bt = (const float*)d_in[7];
    float* out = (float*)d_out;

    void *pn, *pa, *pt;
    cudaGetSymbolAddress(&pn, g_norm);
    cudaGetSymbolAddress(&pa, g_A);
    cudaGetSymbolAddress(&pt, g_top);

    normalize_kernel<<<(BB * NROW) / 8, 256>>>(lf, (float*)pn);

    dim3 gg(NROW / 128, NROW / 128, BB);   // (4,4,8) = 128 CTAs
    gemm_diag_kernel<<<gg, 256>>>((const float*)pn, W, (float*)pa);

    argmax_kernel<<<(BB * NROW) / 8, 256>>>((const float*)pa, (int*)pt);

    conv_ln_kernel<<<BB * NROW, 256>>>(lf, cw, cb, gm, bt, (const int*)pt, out);
}

// round 11
// speedup vs baseline: 1.2552x; 1.2552x over previous
#include <cuda_runtime.h>

// Problem constants
#define CC    512
#define BB    8
#define TT    16
#define ND    32
#define NROW  512           // TT*ND
#define KSZ   7
#define TAU   10            // TT - KSZ + 1
#define LN_EPS 1e-5f
#define NEG_SLOPE 0.01f

// Scratch (no allocations allowed -> __device__ globals)
__device__ float g_inv[BB * NROW];         // per-row inverse L2 norms (16 KB)
__device__ int   g_top[BB * NROW * TT];    // argmax indices

// ---------------- f32x2 (Blackwell packed fp32) helpers ----------------
static __device__ __forceinline__ unsigned long long f2pack(float lo, float hi) {
    unsigned long long r;
    asm("mov.b64 %0, {%1, %2};" : "=l"(r) : "f"(lo), "f"(hi));
    return r;
}
static __device__ __forceinline__ void f2unpack(unsigned long long v, float& lo, float& hi) {
    asm("mov.b64 {%0, %1}, %2;" : "=f"(lo), "=f"(hi) : "l"(v));
}
static __device__ __forceinline__ unsigned long long
f2fma(unsigned long long a, unsigned long long b, unsigned long long c) {
    unsigned long long d;
    asm("fma.rn.f32x2 %0, %1, %2, %3;" : "=l"(d) : "l"(a), "l"(b), "l"(c));
    return d;
}

// ---------------- 1) Row inverse-norm only (one warp per row, 16 KB out) ----------------
__global__ __launch_bounds__(256) void rownorm_kernel(const float* __restrict__ lf,
                                                      float* __restrict__ inv_out) {
    int w = (blockIdx.x * blockDim.x + threadIdx.x) >> 5;
    int lane = threadIdx.x & 31;
    if (w >= BB * NROW) return;
    const float4* src = (const float4*)(lf + (size_t)w * CC);
    float s = 0.f;
#pragma unroll
    for (int q = 0; q < 4; q++) {
        float4 v = src[q * 32 + lane];
        s += v.x * v.x + v.y * v.y + v.z * v.z + v.w * v.w;
    }
#pragma unroll
    for (int off = 16; off; off >>= 1) s += __shfl_xor_sync(0xffffffffu, s, off);
    if (lane == 0) {
        float nrm = sqrtf(s);
        inv_out[w] = 1.0f / fmaxf(nrm, 1e-12f);
    }
}

// ---------------- 2) A=(lf*inv*w)@(lf*inv)^T tile + fused argmax epilogue ----------------
// Double-buffered (register prefetch). Writes ONLY g_top; A never hits global.
__global__ __launch_bounds__(256) void gemm_argmax_kernel(const float* __restrict__ lf,
                                                          const float* __restrict__ W,
                                                          const float* __restrict__ invN,
                                                          int* __restrict__ top) {
    __shared__ float As[16][132];   // transposed: As[k][row] = lf*invR (rounded) * w[k]
    __shared__ float Bs[16][132];   // Bs[k][m]   = lf*invC (rounded)
    __shared__ float wS[CC];        // diag(W)
    __shared__ float invR[128], invC[128];

    const int b = blockIdx.z;
    const int rowBase = blockIdx.y * 128;
    const int colBase = blockIdx.x * 128;
    const int tid = threadIdx.x;
    const int tx = tid & 15;    // 16 col-groups of 8
    const int ty = tid >> 4;    // 16 row-groups of 8

    const float* Ab = lf + (size_t)((b << 9) + rowBase) * CC;   // row tile base
    const float* Bb = lf + (size_t)((b << 9) + colBase) * CC;   // col tile base

    for (int i = tid; i < CC; i += 256) wS[i] = W[(size_t)i * CC + i];
    if (tid < 128) {
        invR[tid] = invN[(b << 9) + rowBase + tid];
        invC[tid] = invN[(b << 9) + colBase + tid];
    }

    unsigned long long acc[8][4];
#pragma unroll
    for (int r = 0; r < 8; r++)
#pragma unroll
        for (int p = 0; p < 4; p++) acc[r][p] = 0ull;

    const int q = tid & 3;      // k float4 index within 16-wide slab
    const int rr = tid >> 2;    // 0..63

    // initial prefetch (k0 = 0)
    float4 pA[2], pB[2];
#pragma unroll
    for (int h = 0; h < 2; h++) {
        pA[h] = *(const float4*)(Ab + (size_t)(rr + h * 64) * CC + q * 4);
        pB[h] = *(const float4*)(Bb + (size_t)(rr + h * 64) * CC + q * 4);
    }
    __syncthreads();   // wS/invR/invC ready

    for (int k0 = 0; k0 < CC; k0 += 16) {
        // store prefetched tiles with scaling (two separate MULs: matches R3 bits)
        {
            float w0 = wS[k0 + q * 4 + 0], w1 = wS[k0 + q * 4 + 1];
            float w2 = wS[k0 + q * 4 + 2], w3 = wS[k0 + q * 4 + 3];
#pragma unroll
            for (int h = 0; h < 2; h++) {
                int row = rr + h * 64;
                float ir = invR[row], ic = invC[row];
                As[q * 4 + 0][row] = (pA[h].x * ir) * w0;
                As[q * 4 + 1][row] = (pA[h].y * ir) * w1;
                As[q * 4 + 2][row] = (pA[h].z * ir) * w2;
                As[q * 4 + 3][row] = (pA[h].w * ir) * w3;
                Bs[q * 4 + 0][row] = pB[h].x * ic;
                Bs[q * 4 + 1][row] = pB[h].y * ic;
                Bs[q * 4 + 2][row] = pB[h].z * ic;
                Bs[q * 4 + 3][row] = pB[h].w * ic;
            }
        }
        __syncthreads();

        // prefetch next slab while computing this one
        if (k0 + 16 < CC) {
#pragma unroll
            for (int h = 0; h < 2; h++) {
                pA[h] = *(const float4*)(Ab + (size_t)(rr + h * 64) * CC + (k0 + 16) + q * 4);
                pB[h] = *(const float4*)(Bb + (size_t)(rr + h * 64) * CC + (k0 + 16) + q * 4);
            }
        }

#pragma unroll
        for (int kk = 0; kk < 16; kk++) {
            float4 a0 = *(const float4*)&As[kk][ty * 8];
            float4 a1 = *(const float4*)&As[kk][ty * 8 + 4];
            float4 b0 = *(const float4*)&Bs[kk][tx * 8];
            float4 b1 = *(const float4*)&Bs[kk][tx * 8 + 4];
            unsigned long long bp[4] = { f2pack(b0.x, b0.y), f2pack(b0.z, b0.w),
                                         f2pack(b1.x, b1.y), f2pack(b1.z, b1.w) };
            float av[8] = { a0.x, a0.y, a0.z, a0.w, a1.x, a1.y, a1.z, a1.w };
#pragma unroll
            for (int r = 0; r < 8; r++) {
                unsigned long long ad = f2pack(av[r], av[r]);
#pragma unroll
                for (int p = 0; p < 4; p++) acc[r][p] = f2fma(ad, bp[p], acc[r][p]);
            }
        }
        __syncthreads();
    }

    // ---- fused argmax epilogue ----
    // Thread owns cols colBase + tx*8 .. +7, all inside one nd-group of 32:
    //   nd = (tx&3)*8 + 2p (+1),   t = colBase/32 + tx/4
    const int ndBase = (tx & 3) * 8;
    const int tIdx = (colBase >> 5) + (tx >> 2);
#pragma unroll
    for (int r = 0; r < 8; r++) {
        float bv = -3.4e38f;
        int bi = 0;
#pragma unroll
        for (int p = 0; p < 4; p++) {
            float lo, hi;
            f2unpack(acc[r][p], lo, hi);
            if (lo > bv) { bv = lo; bi = ndBase + 2 * p; }
            if (hi > bv) { bv = hi; bi = ndBase + 2 * p + 1; }
        }
        // combine the 4 lanes of this nd-group (lanes aligned mod 4)
#pragma unroll
        for (int off = 1; off <= 2; off <<= 1) {
            float ov = __shfl_xor_sync(0xffffffffu, bv, off);
            int oi = __shfl_xor_sync(0xffffffffu, bi, off);
            if (ov > bv || (ov == bv && oi < bi)) { bv = ov; bi = oi; }
        }
        if ((tx & 3) == 0) {
            int rowG = (b << 9) + rowBase + ty * 8 + r;
            top[rowG * TT + tIdx] = bi;
        }
    }
}

// ---------------- 3) gather + depthwise conv + LN + leaky + time-mean (reg-resident) ----
__global__ __launch_bounds__(256, 2) void conv_ln_kernel(const float* __restrict__ lf,
                                                         const float* __restrict__ cw,
                                                         const float* __restrict__ cb,
                                                         const float* __restrict__ gamma,
                                                         const float* __restrict__ beta,
                                                         const int* __restrict__ top,
                                                         float* __restrict__ out) {
    __shared__ int sidx[TT];
    __shared__ float rs[TAU * 8], rss[TAU * 8];

    const int row = blockIdx.x;         // b*512 + n
    const int b = row >> 9;
    const int tid = threadIdx.x;
    const int c0 = tid * 2;

    if (tid < TT) sidx[tid] = top[row * TT + tid];
    __syncthreads();

    // direct coalesced gather into registers: x[t] = lf[b, t, sidx[t], c0..c0+1]
    float2 x[TT];
#pragma unroll
    for (int t = 0; t < TT; t++) {
        const float* src = lf + (((size_t)(b * TT + t)) * ND + sidx[t]) * CC + c0;
        x[t] = *(const float2*)src;
    }

    float2 wv[KSZ];
#pragma unroll
    for (int j = 0; j < KSZ; j++)
        wv[j] = make_float2(cw[c0 * KSZ + j], cw[(c0 + 1) * KSZ + j]);
    const float2 bias = *(const float2*)(cb + c0);

    float2 y[TAU];
    float s[TAU], ss[TAU];
#pragma unroll
    for (int tau = 0; tau < TAU; tau++) {
        float y0 = bias.x, y1 = bias.y;
#pragma unroll
        for (int j = 0; j < KSZ; j++) {
            y0 += wv[j].x * x[tau + j].x;
            y1 += wv[j].y * x[tau + j].y;
        }
        y[tau] = make_float2(y0, y1);
        s[tau] = y0 + y1;
        ss[tau] = y0 * y0 + y1 * y1;
    }

    // batched warp reductions (independent chains -> ILP)
#pragma unroll
    for (int off = 16; off; off >>= 1)
#pragma unroll
        for (int tau = 0; tau < TAU; tau++) {
            s[tau]  += __shfl_xor_sync(0xffffffffu, s[tau],  off);
            ss[tau] += __shfl_xor_sync(0xffffffffu, ss[tau], off);
        }
    const int lane = tid & 31, warp = tid >> 5;
    if (lane == 0) {
#pragma unroll
        for (int tau = 0; tau < TAU; tau++) {
            rs[tau * 8 + warp] = s[tau];
            rss[tau * 8 + warp] = ss[tau];
        }
    }
    __syncthreads();

    const float2 gm = *(const float2*)(gamma + c0);
    const float2 be = *(const float2*)(beta + c0);
    float acc0 = 0.f, acc1 = 0.f;
#pragma unroll
    for (int tau = 0; tau < TAU; tau++) {
        float S = 0.f, SS = 0.f;
#pragma unroll
        for (int k = 0; k < 8; k++) { S += rs[tau * 8 + k]; SS += rss[tau * 8 + k]; }
        float mu = S * (1.0f / 512.0f);
        float var = SS * (1.0f / 512.0f) - mu * mu;
        float inv = rsqrtf(var + LN_EPS);
        float l0 = (y[tau].x - mu) * inv * gm.x + be.x;
        float l1 = (y[tau].y - mu) * inv * gm.y + be.y;
        acc0 += (l0 >= 0.f) ? l0 : NEG_SLOPE * l0;
        acc1 += (l1 >= 0.f) ? l1 : NEG_SLOPE * l1;
    }
    *(float2*)(out + (size_t)row * CC + c0) =
        make_float2(acc0 * (1.0f / TAU), acc1 * (1.0f / TAU));
}

// ---------------- launch ----------------
extern "C" void kernel_launch(void* const* d_in, const int* in_sizes, int n_in,
                              void* d_out, int out_size) {
    const float* lf = (const float*)d_in[0];   // local_feat (8,16,32,512)
    // d_in[1] global_feat, d_in[2] pos: unused by the reference
    const float* W  = (const float*)d_in[3];
    const float* cw = (const float*)d_in[4];
    const float* cb = (const float*)d_in[5];
    const float* gm = (const float*)d_in[6];
    const float* bt = (const float*)d_in[7];
    float* out = (float*)d_out;

    void *pi, *pt;
    cudaGetSymbolAddress(&pi, g_inv);
    cudaGetSymbolAddress(&pt, g_top);

    rownorm_kernel<<<(BB * NROW) / 8, 256>>>(lf, (float*)pi);

    dim3 gg(NROW / 128, NROW / 128, BB);   // (4,4,8) = 128 CTAs
    gemm_argmax_kernel<<<gg, 256>>>(lf, W, (const float*)pi, (int*)pt);

    conv_ln_kernel<<<BB * NROW, 256>>>(lf, cw, cb, gm, bt, (const int*)pt, out);
}